// round 1
// baseline (speedup 1.0000x reference)
#include <cuda_runtime.h>

#define BATCH   1024
#define TSTEPS  100
#define L0      30
#define C1      16
#define L1      24
#define K1      7
#define C2      32
#define L2      20
#define K2      5
#define C3      64
#define L3      18
#define K3      3
#define F1      1152   // 64*18
#define H1      256
#define NC      10

#define NTHREADS 256

// Transposed fc1 weights: fw1T[i*H1 + j] = fw1[j*F1 + i]   (i: input, j: output)
__device__ float g_fw1T[F1 * H1];

__global__ void transpose_fw1_kernel(const float* __restrict__ fw1) {
    int idx = blockIdx.x * blockDim.x + threadIdx.x;
    if (idx < H1 * F1) {
        int j = idx / F1;
        int i = idx - j * F1;
        g_fw1T[i * H1 + j] = fw1[idx];
    }
}

// LIF: reset from PREVIOUS mem (subtract mechanism), then spike on new mem.
// No FMA contraction: match reference op sequence  0.9*m + h - reset.
__device__ __forceinline__ float lif_step(float* mem, float h) {
    float m = *mem;
    float reset = (m > 1.0f) ? 1.0f : 0.0f;
    m = __fadd_rn(__fadd_rn(__fmul_rn(0.9f, m), h), -reset);
    *mem = m;
    return (m > 1.0f) ? 1.0f : 0.0f;
}

#define SMEM_WORDS 20792
#define SMEM_BYTES (SMEM_WORDS * 4)

__global__ __launch_bounds__(NTHREADS, 2)
void snn_kernel(const float* __restrict__ x,
                const float* __restrict__ w1, const float* __restrict__ b1,
                const float* __restrict__ w2, const float* __restrict__ b2,
                const float* __restrict__ w3, const float* __restrict__ b3,
                const float* __restrict__ fb1,
                const float* __restrict__ fw2, const float* __restrict__ fb2,
                float* __restrict__ out)
{
    extern __shared__ float smem[];
    float* sw1t = smem;                    // [K1][C1]          112
    float* sb1  = sw1t + K1 * C1;          //                    16
    float* sw2t = sb1 + C1;                // [(ci*K2+k)][C2]  2560
    float* sb2  = sw2t + C1 * K2 * C2;     //                    32
    float* sw3t = sb2 + C2;                // [(ci*K3+k)][C3]  6144
    float* sb3  = sw3t + C2 * K3 * C3;     //                    64
    float* sfw2 = sb3 + C3;                // [j][i]           2560
    float* sfb2 = sfw2 + NC * H1;          //                    16 (pad)
    float* sfb1 = sfb2 + 16;               //                   256
    float* sx   = sfb1 + H1;               // [l][t]           3000
    float* m1   = sx + L0 * TSTEPS;        //                   384
    float* m2   = m1 + C1 * L1;            //                   640
    float* m3   = m2 + C2 * L2;            //                  1152
    float* m4   = m3 + C3 * L3;            //                   256
    float* m5   = m4 + H1;                 //                    16 (pad)
    float* s1   = m5 + 16;                 //                   384
    float* s2   = s1 + C1 * L1;            //                   640
    float* s3   = s2 + C2 * L2;            //                  1152
    float* s4   = s3 + C3 * L3;            //                   256
    int*   act  = (int*)(s4 + H1);         //                  1152 ints
    __shared__ int n_act;

    const int tid = threadIdx.x;
    const int b = blockIdx.x;

    // ---- load weights into smem (transposed so warp lanes = out-channel) ----
    for (int i = tid; i < C1 * K1; i += NTHREADS) {
        int co = i / K1, k = i - co * K1;
        sw1t[k * C1 + co] = w1[i];
    }
    for (int i = tid; i < C2 * C1 * K2; i += NTHREADS) {
        int co = i / (C1 * K2), r = i - co * (C1 * K2);  // r = ci*K2 + k
        sw2t[r * C2 + co] = w2[i];
    }
    for (int i = tid; i < C3 * C2 * K3; i += NTHREADS) {
        int co = i / (C2 * K3), r = i - co * (C2 * K3);  // r = ci*K3 + k
        sw3t[r * C3 + co] = w3[i];
    }
    for (int i = tid; i < NC * H1; i += NTHREADS) sfw2[i] = fw2[i];
    for (int i = tid; i < H1; i += NTHREADS) sfb1[i] = fb1[i];
    if (tid < C1) sb1[tid] = b1[tid];
    if (tid < C2) sb2[tid] = b2[tid];
    if (tid < C3) sb3[tid] = b3[tid];
    if (tid < NC) sfb2[tid] = fb2[tid];
    // this sample's input: x[b,0,l,t], contiguous 3000 floats
    for (int i = tid; i < L0 * TSTEPS; i += NTHREADS) sx[i] = x[b * (L0 * TSTEPS) + i];
    // zero membrane state
    for (int i = tid; i < C1 * L1; i += NTHREADS) m1[i] = 0.0f;
    for (int i = tid; i < C2 * L2; i += NTHREADS) m2[i] = 0.0f;
    for (int i = tid; i < C3 * L3; i += NTHREADS) m3[i] = 0.0f;
    for (int i = tid; i < H1; i += NTHREADS) m4[i] = 0.0f;
    if (tid < NC) m5[tid] = 0.0f;
    __syncthreads();

    const int lane = tid & 31;
    const int warp = tid >> 5;

    for (int t = 0; t < TSTEPS; t++) {
        // ---------------- conv1 (1->16, k=7, 30->24) + LIF ----------------
        for (int idx = tid; idx < C1 * L1; idx += NTHREADS) {
            int l = idx >> 4, co = idx & 15;
            float acc = sb1[co];
            #pragma unroll
            for (int k = 0; k < K1; k++)
                acc = fmaf(sw1t[k * C1 + co], sx[(l + k) * TSTEPS + t], acc);
            int lin = co * L1 + l;
            s1[lin] = lif_step(&m1[lin], acc);
        }
        __syncthreads();

        // ---------------- conv2 (16->32, k=5, 24->20) + LIF ----------------
        // thread = (lg, co): warp shares lg -> spike loads broadcast,
        // weight loads coalesced over co. 8 groups over 20 positions {3x4,2x4}.
        {
            int co = tid & 31;
            int lg = tid >> 5;
            int l0  = (lg < 4) ? lg * 3 : 12 + (lg - 4) * 2;
            int len = (lg < 4) ? 3 : 2;
            float acc0 = sb2[co], acc1 = acc0, acc2 = acc0;
            for (int ci = 0; ci < C1; ci++) {
                const float* sp = &s1[ci * L1 + l0];
                const float* wp = &sw2t[ci * K2 * C2 + co];
                float sv[K2 + 2];
                #pragma unroll
                for (int d = 0; d < K2 + 2; d++) sv[d] = sp[d];  // may bleed 1 into s2 region; result discarded
                #pragma unroll
                for (int k = 0; k < K2; k++) {
                    float w = wp[k * C2];
                    acc0 = fmaf(w, sv[k], acc0);
                    acc1 = fmaf(w, sv[k + 1], acc1);
                    acc2 = fmaf(w, sv[k + 2], acc2);
                }
            }
            float accs[3] = {acc0, acc1, acc2};
            for (int q = 0; q < len; q++) {
                int lin = co * L2 + l0 + q;
                s2[lin] = lif_step(&m2[lin], accs[q]);
            }
        }
        __syncthreads();

        // ---------------- conv3 (32->64, k=3, 20->18) + LIF ----------------
        // 4 groups over 18 positions {5,5,4,4}; warp shares lg.
        {
            int co = tid & 63;
            int lg = tid >> 6;
            int l0  = (lg < 2) ? lg * 5 : 10 + (lg - 2) * 4;
            int len = (lg < 2) ? 5 : 4;
            float acc0 = sb3[co], acc1 = acc0, acc2 = acc0, acc3 = acc0, acc4 = acc0;
            for (int ci = 0; ci < C2; ci++) {
                const float* sp = &s2[ci * L2 + l0];
                const float* wp = &sw3t[ci * K3 * C3 + co];
                float sv[K3 + 4];
                #pragma unroll
                for (int d = 0; d < K3 + 4; d++) sv[d] = sp[d];  // may bleed 1 into s3 region; discarded
                #pragma unroll
                for (int k = 0; k < K3; k++) {
                    float w = wp[k * C3];
                    acc0 = fmaf(w, sv[k], acc0);
                    acc1 = fmaf(w, sv[k + 1], acc1);
                    acc2 = fmaf(w, sv[k + 2], acc2);
                    acc3 = fmaf(w, sv[k + 3], acc3);
                    acc4 = fmaf(w, sv[k + 4], acc4);
                }
            }
            if (tid == 0) n_act = 0;   // reset active counter before barrier
            float accs[5] = {acc0, acc1, acc2, acc3, acc4};
            for (int q = 0; q < len; q++) {
                int lin = co * L3 + l0 + q;
                s3[lin] = lif_step(&m3[lin], accs[q]);
            }
        }
        __syncthreads();

        // ---------------- build active-spike list for fc1 ----------------
        for (int i = tid; i < F1; i += NTHREADS) {
            if (s3[i] != 0.0f) {
                int p = atomicAdd(&n_act, 1);
                act[p] = i;
            }
        }
        __syncthreads();

        // ---------------- fc1 (1152->256) sparse gather + LIF ----------------
        {
            int j = tid;  // exactly 256 outputs
            float acc = sfb1[j];
            int na = n_act;
            int a = 0;
            for (; a + 4 <= na; a += 4) {
                int i0 = act[a], i1 = act[a + 1], i2 = act[a + 2], i3 = act[a + 3];
                float v0 = __ldg(&g_fw1T[i0 * H1 + j]);
                float v1 = __ldg(&g_fw1T[i1 * H1 + j]);
                float v2 = __ldg(&g_fw1T[i2 * H1 + j]);
                float v3 = __ldg(&g_fw1T[i3 * H1 + j]);
                acc += v0; acc += v1; acc += v2; acc += v3;
            }
            for (; a < na; a++) acc += __ldg(&g_fw1T[act[a] * H1 + j]);
            s4[j] = lif_step(&m4[j], acc);
        }
        __syncthreads();

        // ---------------- fc2 (256->10) + LIF + output ----------------
        for (int j = warp; j < NC; j += 8) {
            float acc = 0.0f;
            #pragma unroll
            for (int i = lane; i < H1; i += 32)
                acc = fmaf(sfw2[j * H1 + i], s4[i], acc);
            #pragma unroll
            for (int o = 16; o > 0; o >>= 1)
                acc += __shfl_down_sync(0xffffffff, acc, o);
            if (lane == 0) {
                acc += sfb2[j];
                float sp = lif_step(&m5[j], acc);
                out[(t * BATCH + b) * NC + j] = sp;
            }
        }
        __syncthreads();
    }
}

extern "C" void kernel_launch(void* const* d_in, const int* in_sizes, int n_in,
                              void* d_out, int out_size) {
    const float* x   = (const float*)d_in[0];
    const float* w1  = (const float*)d_in[1];
    const float* b1  = (const float*)d_in[2];
    const float* w2  = (const float*)d_in[3];
    const float* b2  = (const float*)d_in[4];
    const float* w3  = (const float*)d_in[5];
    const float* b3  = (const float*)d_in[6];
    const float* fw1 = (const float*)d_in[7];
    const float* fb1 = (const float*)d_in[8];
    const float* fw2 = (const float*)d_in[9];
    const float* fb2 = (const float*)d_in[10];
    float* out = (float*)d_out;

    cudaFuncSetAttribute(snn_kernel, cudaFuncAttributeMaxDynamicSharedMemorySize, SMEM_BYTES);

    transpose_fw1_kernel<<<(H1 * F1 + 255) / 256, 256>>>(fw1);
    snn_kernel<<<BATCH, NTHREADS, SMEM_BYTES>>>(x, w1, b1, w2, b2, w3, b3,
                                                fb1, fw2, fb2, out);
}

// round 2
// speedup vs baseline: 1.2945x; 1.2945x over previous
#include <cuda_runtime.h>

#define BATCH   1024
#define TSTEPS  100
#define L0      30
#define C1      16
#define L1      24
#define K1      7
#define C2      32
#define L2      20
#define K2      5
#define C3      64
#define L3      18
#define K3      3
#define F1      1152   // 64*18
#define H1      256
#define NC      10

#define NTHREADS 256

// Transposed fc1 weights: fw1T[i*H1 + j] = fw1[j*F1 + i]
__device__ float g_fw1T[F1 * H1];

__global__ void transpose_fw1_kernel(const float* __restrict__ fw1) {
    int idx = blockIdx.x * blockDim.x + threadIdx.x;
    if (idx < H1 * F1) {
        int j = idx / F1;
        int i = idx - j * F1;
        g_fw1T[i * H1 + j] = fw1[idx];
    }
}

// LIF: reset from PREVIOUS mem (subtract), spike on new mem.
// No FMA contraction: match reference op sequence 0.9*m + h - reset.
__device__ __forceinline__ float lif_new_mem(float m_old, float h) {
    float reset = (m_old > 1.0f) ? 1.0f : 0.0f;
    return __fadd_rn(__fadd_rn(__fmul_rn(0.9f, m_old), h), -reset);
}

#define SMEM_WORDS 17576
#define SMEM_BYTES (SMEM_WORDS * 4)

__global__ __launch_bounds__(NTHREADS, 3)
void snn_kernel(const float* __restrict__ x,
                const float* __restrict__ w1, const float* __restrict__ b1,
                const float* __restrict__ w2, const float* __restrict__ b2,
                const float* __restrict__ w3, const float* __restrict__ b3,
                const float* __restrict__ fb1,
                const float* __restrict__ fw2, const float* __restrict__ fb2,
                float* __restrict__ out)
{
    extern __shared__ float smem[];
    float* sw1t = smem;                     // [k][co]            112
    float* sb1  = sw1t + K1 * C1;           //                     16
    float* sw2t = sb1 + C1;                 // [(ci*K2+k)][co]   2560
    float* sb2  = sw2t + C1 * K2 * C2;      //                     32
    float* sw3t = sb2 + C2;                 // [(ci*K3+k)][co]   6144
    float* sb3  = sw3t + C2 * K3 * C3;      //                     64
    float* sfw2 = sb3 + C3;                 // [j][i]            2560
    float* sfb2 = sfw2 + NC * H1;           //                     16 (pad)
    float* sfb1 = sfb2 + 16;                //                    256
    float* sx   = sfb1 + H1;                // [l][t]            3000
    float* m1   = sx + L0 * TSTEPS;         // [l][co]            384
    float* m2   = m1 + C1 * L1;             // [l][co]            640
    float* m3   = m2 + C2 * L2;             // [l][co]           1152
    float* m4   = m3 + C3 * L3;             //                    256
    float* m5   = m4 + H1;                  //                     16 (pad)
    float* s4   = m5 + 16;                  //                    256
    unsigned* umask = (unsigned*)(s4 + H1); // mask1(16) mask2(32) mask3(64) = 112
    unsigned* mask1 = umask;
    unsigned* mask2 = umask + C1;
    unsigned* mask3 = umask + C1 + C2;

    const int tid = threadIdx.x;
    const int b = blockIdx.x;

    // ---- load weights into smem (transposed: lanes = out-channel) ----
    for (int i = tid; i < C1 * K1; i += NTHREADS) {
        int co = i / K1, k = i - co * K1;
        sw1t[k * C1 + co] = w1[i];
    }
    for (int i = tid; i < C2 * C1 * K2; i += NTHREADS) {
        int co = i / (C1 * K2), r = i - co * (C1 * K2);
        sw2t[r * C2 + co] = w2[i];
    }
    for (int i = tid; i < C3 * C2 * K3; i += NTHREADS) {
        int co = i / (C2 * K3), r = i - co * (C2 * K3);
        sw3t[r * C3 + co] = w3[i];
    }
    for (int i = tid; i < NC * H1; i += NTHREADS) sfw2[i] = fw2[i];
    for (int i = tid; i < H1; i += NTHREADS) sfb1[i] = fb1[i];
    if (tid < C1) sb1[tid] = b1[tid];
    if (tid < C2) sb2[tid] = b2[tid];
    if (tid < C3) sb3[tid] = b3[tid];
    if (tid < NC) sfb2[tid] = fb2[tid];
    for (int i = tid; i < L0 * TSTEPS; i += NTHREADS) sx[i] = x[b * (L0 * TSTEPS) + i];
    for (int i = tid; i < C1 * L1; i += NTHREADS) m1[i] = 0.0f;
    for (int i = tid; i < C2 * L2; i += NTHREADS) m2[i] = 0.0f;
    for (int i = tid; i < C3 * L3; i += NTHREADS) m3[i] = 0.0f;
    for (int i = tid; i < H1; i += NTHREADS) m4[i] = 0.0f;
    if (tid < NC) m5[tid] = 0.0f;
    __syncthreads();

    const int lane = tid & 31;
    const int warp = tid >> 5;

    for (int t = 0; t < TSTEPS; t++) {
        // zero spike masks for this timestep
        if (tid < C1 + C2 + C3) umask[tid] = 0u;
        __syncthreads();

        // ---------------- conv1 (1->16, k=7, 30->24) + LIF -> mask1 ----------------
        #pragma unroll
        for (int it = 0; it < 2; it++) {
            int idx = tid + it * NTHREADS;
            if (idx < C1 * L1) {
                int l = idx >> 4, co = idx & 15;
                float acc = sb1[co];
                #pragma unroll
                for (int k = 0; k < K1; k++)
                    acc = fmaf(sw1t[k * C1 + co], sx[(l + k) * TSTEPS + t], acc);
                float mn = lif_new_mem(m1[idx], acc);
                m1[idx] = mn;
                if (mn > 1.0f) atomicOr(&mask1[co], 1u << l);
            }
        }
        __syncthreads();

        // ---------------- conv2 (16->32, k=5, 24->20) + LIF -> mask2 ----------------
        {
            int co = tid & 31;
            int lg = tid >> 5;
            int l0  = (lg < 4) ? lg * 3 : 12 + (lg - 4) * 2;
            int len = (lg < 4) ? 3 : 2;
            float acc0 = sb2[co], acc1 = acc0, acc2 = acc0;
            #pragma unroll
            for (int ci = 0; ci < C1; ci++) {
                unsigned mrow = mask1[ci] >> l0;
                const float* wp = &sw2t[ci * (K2 * C2) + co];
                #pragma unroll
                for (int k = 0; k < K2; k++) {
                    float w = wp[k * C2];
                    if (mrow & (1u << k)) acc0 += w;
                    if (mrow & (2u << k)) acc1 += w;
                    if (mrow & (4u << k)) acc2 += w;
                }
            }
            float accs[3] = {acc0, acc1, acc2};
            unsigned bits = 0;
            #pragma unroll
            for (int q = 0; q < 3; q++) {
                if (q < len) {
                    int lin = (l0 + q) * C2 + co;
                    float mn = lif_new_mem(m2[lin], accs[q]);
                    m2[lin] = mn;
                    if (mn > 1.0f) bits |= 1u << q;
                }
            }
            if (bits) atomicOr(&mask2[co], bits << l0);
        }
        __syncthreads();

        // ---------------- conv3 (32->64, k=3, 20->18) + LIF -> mask3 ----------------
        {
            int co = tid & 63;
            int lg = tid >> 6;
            int l0  = (lg < 2) ? lg * 5 : 10 + (lg - 2) * 4;
            int len = (lg < 2) ? 5 : 4;
            float acc0 = sb3[co], acc1 = acc0, acc2 = acc0, acc3 = acc0, acc4 = acc0;
            #pragma unroll
            for (int ci = 0; ci < C2; ci++) {
                unsigned mrow = mask2[ci] >> l0;
                const float* wp = &sw3t[ci * (K3 * C3) + co];
                #pragma unroll
                for (int k = 0; k < K3; k++) {
                    float w = wp[k * C3];
                    if (mrow & (1u  << k)) acc0 += w;
                    if (mrow & (2u  << k)) acc1 += w;
                    if (mrow & (4u  << k)) acc2 += w;
                    if (mrow & (8u  << k)) acc3 += w;
                    if (mrow & (16u << k)) acc4 += w;
                }
            }
            float accs[5] = {acc0, acc1, acc2, acc3, acc4};
            unsigned bits = 0;
            #pragma unroll
            for (int q = 0; q < 5; q++) {
                if (q < len) {
                    int lin = (l0 + q) * C3 + co;
                    float mn = lif_new_mem(m3[lin], accs[q]);
                    m3[lin] = mn;
                    if (mn > 1.0f) bits |= 1u << q;
                }
            }
            if (bits) atomicOr(&mask3[co], bits << l0);
        }
        __syncthreads();

        // ---------------- fc1 (1152->256) sparse gather from mask3 + LIF ----------------
        {
            int j = tid;  // 256 outputs
            float acc = sfb1[j];
            #pragma unroll 4
            for (int r = 0; r < C3; r++) {
                unsigned m = mask3[r];   // broadcast; uniform across block
                const float* wbase = &g_fw1T[r * (L3 * H1) + j];
                while (m) {
                    int l = __ffs(m) - 1;
                    m &= m - 1;
                    acc += __ldg(&wbase[l * H1]);
                }
            }
            float mn = lif_new_mem(m4[j], acc);
            m4[j] = mn;
            s4[j] = (mn > 1.0f) ? 1.0f : 0.0f;
        }
        __syncthreads();

        // ---------------- fc2 (256->10) + LIF + output ----------------
        for (int j = warp; j < NC; j += 8) {
            float acc = 0.0f;
            #pragma unroll
            for (int i = lane; i < H1; i += 32)
                acc = fmaf(sfw2[j * H1 + i], s4[i], acc);
            #pragma unroll
            for (int o = 16; o > 0; o >>= 1)
                acc += __shfl_down_sync(0xffffffff, acc, o);
            if (lane == 0) {
                acc += sfb2[j];
                float mn = lif_new_mem(m5[j], acc);
                m5[j] = mn;
                out[(t * BATCH + b) * NC + j] = (mn > 1.0f) ? 1.0f : 0.0f;
            }
        }
        __syncthreads();
    }
}

extern "C" void kernel_launch(void* const* d_in, const int* in_sizes, int n_in,
                              void* d_out, int out_size) {
    const float* x   = (const float*)d_in[0];
    const float* w1  = (const float*)d_in[1];
    const float* b1  = (const float*)d_in[2];
    const float* w2  = (const float*)d_in[3];
    const float* b2  = (const float*)d_in[4];
    const float* w3  = (const float*)d_in[5];
    const float* b3  = (const float*)d_in[6];
    const float* fw1 = (const float*)d_in[7];
    const float* fb1 = (const float*)d_in[8];
    const float* fw2 = (const float*)d_in[9];
    const float* fb2 = (const float*)d_in[10];
    float* out = (float*)d_out;

    cudaFuncSetAttribute(snn_kernel, cudaFuncAttributeMaxDynamicSharedMemorySize, SMEM_BYTES);

    transpose_fw1_kernel<<<(H1 * F1 + 255) / 256, 256>>>(fw1);
    snn_kernel<<<BATCH, NTHREADS, SMEM_BYTES>>>(x, w1, b1, w2, b2, w3, b3,
                                                fb1, fw2, fb2, out);
}

// round 3
// speedup vs baseline: 1.3683x; 1.0570x over previous
#include <cuda_runtime.h>

#define BATCH   1024
#define TSTEPS  100
#define L0      30
#define C1      16
#define L1      24
#define K1      7
#define C2      32
#define L2      20
#define K2      5
#define C3      64
#define L3      18
#define K3      3
#define F1      1152   // 64*18
#define H1      256
#define NC      10

#define NTHREADS 256

typedef unsigned long long u64;

// Transposed fc1 weights: fw1T[i*H1 + j] = fw1[j*F1 + i]
__device__ float g_fw1T[F1 * H1];

__global__ void transpose_fw1_kernel(const float* __restrict__ fw1) {
    int idx = blockIdx.x * blockDim.x + threadIdx.x;
    if (idx < H1 * F1) {
        int j = idx / F1;
        int i = idx - j * F1;
        g_fw1T[i * H1 + j] = fw1[idx];
    }
}

// ---- f32x2 helpers ----
__device__ __forceinline__ u64 ffma2(u64 a, u64 b, u64 c) {
    u64 d; asm("fma.rn.f32x2 %0, %1, %2, %3;" : "=l"(d) : "l"(a), "l"(b), "l"(c)); return d;
}
__device__ __forceinline__ u64 fadd2(u64 a, u64 b) {
    u64 d; asm("add.rn.f32x2 %0, %1, %2;" : "=l"(d) : "l"(a), "l"(b)); return d;
}
__device__ __forceinline__ u64 pack2(float lo, float hi) {
    u64 r; asm("mov.b64 %0, {%1, %2};" : "=l"(r) : "f"(lo), "f"(hi)); return r;
}
__device__ __forceinline__ void unpack2(u64 v, float& lo, float& hi) {
    asm("mov.b64 {%0, %1}, %2;" : "=f"(lo), "=f"(hi) : "l"(v));
}
__device__ __forceinline__ u64 lds64(const float* p) {
    return *(const u64*)p;
}

// LIF: reset from PREVIOUS mem (subtract), spike on new mem.
// No FMA contraction: match reference op sequence 0.9*m + h - reset.
__device__ __forceinline__ float lif_new_mem(float m_old, float h) {
    float reset = (m_old > 1.0f) ? 1.0f : 0.0f;
    return __fadd_rn(__fadd_rn(__fmul_rn(0.9f, m_old), h), -reset);
}

#define SMEM_WORDS 12800
#define SMEM_BYTES (SMEM_WORDS * 4)

__global__ __launch_bounds__(NTHREADS, 4)
void snn_kernel(const float* __restrict__ x,
                const float* __restrict__ w1, const float* __restrict__ b1,
                const float* __restrict__ w2, const float* __restrict__ b2,
                const float* __restrict__ w3, const float* __restrict__ b3,
                const float* __restrict__ fb1,
                const float* __restrict__ fw2, const float* __restrict__ fb2,
                float* __restrict__ out)
{
    extern __shared__ float smem[];
    float* sw1t = smem;                     // [k][co]                 112
    float* sb1  = sw1t + K1 * C1;           //                          16
    float* sw2p = sb1 + C1;                 // [((p*5+k)*32+co)*2+e]  2560
    float* sb2  = sw2p + C1 * K2 * C2;      //                          32
    float* sw3p = sb2 + C2;                 // [((p*3+k)*64+co)*2+e]  6144
    float* sb3  = sw3p + C2 * K3 * C3;      //                          64
    float* xbuf = sb3 + C3;                 // [2][32]                  64
    float* m1   = xbuf + 64;                // [l*16+co]               384
    float* m2   = m1 + C1 * L1;             // [l*32+co]               640
    float* m3   = m2 + C2 * L2;             // [l*64+co]              1152
    float* m4   = m3 + C3 * L3;             //                         256
    float* m5   = m4 + H1;                  //                          16
    float* s1   = m5 + 16;                  // [l][ci]                 384
    float* s2   = s1 + C1 * L1;             // [l][ci]                 640
    float* s4   = s2 + C2 * L2;             //                         256
    unsigned* mask3 = (unsigned*)(s4 + H1); //                          64

    const int tid = threadIdx.x;
    const int b = blockIdx.x;
    const int lane = tid & 31;
    const int warp = tid >> 5;

    // ---- load weights into smem ----
    for (int i = tid; i < C1 * K1; i += NTHREADS) {
        int co = i / K1, k = i - co * K1;
        sw1t[k * C1 + co] = w1[i];
    }
    // w2: (32,16,5) -> pair-interleaved [((p*5+k)*32+co)*2+e], ci=2p+e
    for (int i = tid; i < C2 * C1 * K2; i += NTHREADS) {
        int co = i / (C1 * K2);
        int r = i - co * (C1 * K2);
        int ci = r / K2, k = r - ci * K2;
        sw2p[(( (ci >> 1) * K2 + k) * C2 + co) * 2 + (ci & 1)] = w2[i];
    }
    // w3: (64,32,3) -> [((p*3+k)*64+co)*2+e]
    for (int i = tid; i < C3 * C2 * K3; i += NTHREADS) {
        int co = i / (C2 * K3);
        int r = i - co * (C2 * K3);
        int ci = r / K3, k = r - ci * K3;
        sw3p[(( (ci >> 1) * K3 + k) * C3 + co) * 2 + (ci & 1)] = w3[i];
    }
    if (tid < C1) sb1[tid] = b1[tid];
    if (tid < C2) sb2[tid] = b2[tid];
    if (tid < C3) sb3[tid] = b3[tid];
    // zero membrane state
    for (int i = tid; i < C1 * L1; i += NTHREADS) m1[i] = 0.0f;
    for (int i = tid; i < C2 * L2; i += NTHREADS) m2[i] = 0.0f;
    for (int i = tid; i < C3 * L3; i += NTHREADS) m3[i] = 0.0f;
    for (int i = tid; i < H1; i += NTHREADS) m4[i] = 0.0f;
    if (tid < NC) m5[tid] = 0.0f;
    // preload x for t=0
    if (warp == 7 && lane < L0) xbuf[lane] = x[b * (L0 * TSTEPS) + lane * TSTEPS];
    __syncthreads();

    for (int t = 0; t < TSTEPS; t++) {
        // zero mask3; prefetch x for t+1 into other buffer
        if (tid < C3) mask3[tid] = 0u;
        if (warp == 7 && lane < L0 && t + 1 < TSTEPS)
            xbuf[((t + 1) & 1) * 32 + lane] = x[b * (L0 * TSTEPS) + lane * TSTEPS + t + 1];
        const float* xc = xbuf + (t & 1) * 32;
        __syncthreads();

        // ---------------- conv1 (1->16, k=7, 30->24) + LIF -> s1 floats ----------------
        #pragma unroll
        for (int it = 0; it < 2; it++) {
            int idx = tid + it * NTHREADS;
            if (idx < C1 * L1) {
                int l = idx >> 4, co = idx & 15;
                float acc = sb1[co];
                #pragma unroll
                for (int k = 0; k < K1; k++)
                    acc = fmaf(sw1t[k * C1 + co], xc[l + k], acc);
                float mn = lif_new_mem(m1[idx], acc);
                m1[idx] = mn;
                s1[idx] = (mn > 1.0f) ? 1.0f : 0.0f;   // [l][ci] layout
            }
        }
        __syncthreads();

        // ---------------- conv2 (16->32, k=5, 24->20) + LIF -> s2 floats ----------------
        // groups (even starts): g0:l0=0 len4, g1:4 len4, g2..g7: 8,10,12,14,16,18 len2
        {
            int co = tid & 31;
            int g  = tid >> 5;
            float bias = sb2[co];
            if (g < 2) {
                int l0 = g * 4;
                u64 a0 = pack2(bias, 0.0f), a1 = a0, a2 = a0, a3 = a0;
                #pragma unroll
                for (int p = 0; p < 8; p++) {
                    u64 sp[8];
                    #pragma unroll
                    for (int d = 0; d < 8; d++) sp[d] = lds64(s1 + (l0 + d) * C1 + 2 * p);
                    #pragma unroll
                    for (int k = 0; k < K2; k++) {
                        u64 w = lds64(sw2p + ((p * K2 + k) * C2 + co) * 2);
                        a0 = ffma2(w, sp[k], a0);
                        a1 = ffma2(w, sp[k + 1], a1);
                        a2 = ffma2(w, sp[k + 2], a2);
                        a3 = ffma2(w, sp[k + 3], a3);
                    }
                }
                u64 accs[4] = {a0, a1, a2, a3};
                #pragma unroll
                for (int q = 0; q < 4; q++) {
                    float lo, hi; unpack2(accs[q], lo, hi);
                    float h = __fadd_rn(lo, hi);
                    int lin = (l0 + q) * C2 + co;
                    float mn = lif_new_mem(m2[lin], h);
                    m2[lin] = mn;
                    s2[lin] = (mn > 1.0f) ? 1.0f : 0.0f;
                }
            } else {
                int l0 = 8 + (g - 2) * 2;
                u64 a0 = pack2(bias, 0.0f), a1 = a0;
                #pragma unroll
                for (int p = 0; p < 8; p++) {
                    u64 sp[6];
                    #pragma unroll
                    for (int d = 0; d < 6; d++) sp[d] = lds64(s1 + (l0 + d) * C1 + 2 * p);
                    #pragma unroll
                    for (int k = 0; k < K2; k++) {
                        u64 w = lds64(sw2p + ((p * K2 + k) * C2 + co) * 2);
                        a0 = ffma2(w, sp[k], a0);
                        a1 = ffma2(w, sp[k + 1], a1);
                    }
                }
                u64 accs[2] = {a0, a1};
                #pragma unroll
                for (int q = 0; q < 2; q++) {
                    float lo, hi; unpack2(accs[q], lo, hi);
                    float h = __fadd_rn(lo, hi);
                    int lin = (l0 + q) * C2 + co;
                    float mn = lif_new_mem(m2[lin], h);
                    m2[lin] = mn;
                    s2[lin] = (mn > 1.0f) ? 1.0f : 0.0f;
                }
            }
        }
        __syncthreads();

        // ---------------- conv3 (32->64, k=3, 20->18) + LIF -> mask3 bits ----------------
        // groups (even starts): g0:l0=0 len6, g1:6 len4, g2:10 len4, g3:14 len4
        {
            int co = tid & 63;
            int g  = tid >> 6;
            float bias = sb3[co];
            if (g == 0) {
                u64 a0 = pack2(bias, 0.0f), a1 = a0, a2 = a0, a3 = a0, a4 = a0, a5 = a0;
                #pragma unroll
                for (int p = 0; p < 16; p++) {
                    u64 sp[8];
                    #pragma unroll
                    for (int d = 0; d < 8; d++) sp[d] = lds64(s2 + d * C2 + 2 * p);
                    #pragma unroll
                    for (int k = 0; k < K3; k++) {
                        u64 w = lds64(sw3p + ((p * K3 + k) * C3 + co) * 2);
                        a0 = ffma2(w, sp[k], a0);
                        a1 = ffma2(w, sp[k + 1], a1);
                        a2 = ffma2(w, sp[k + 2], a2);
                        a3 = ffma2(w, sp[k + 3], a3);
                        a4 = ffma2(w, sp[k + 4], a4);
                        a5 = ffma2(w, sp[k + 5], a5);
                    }
                }
                u64 accs[6] = {a0, a1, a2, a3, a4, a5};
                unsigned bits = 0;
                #pragma unroll
                for (int q = 0; q < 6; q++) {
                    float lo, hi; unpack2(accs[q], lo, hi);
                    float h = __fadd_rn(lo, hi);
                    int lin = q * C3 + co;
                    float mn = lif_new_mem(m3[lin], h);
                    m3[lin] = mn;
                    if (mn > 1.0f) bits |= 1u << q;
                }
                if (bits) atomicOr(&mask3[co], bits);
            } else {
                int l0 = 6 + (g - 1) * 4;
                u64 a0 = pack2(bias, 0.0f), a1 = a0, a2 = a0, a3 = a0;
                #pragma unroll
                for (int p = 0; p < 16; p++) {
                    u64 sp[6];
                    #pragma unroll
                    for (int d = 0; d < 6; d++) sp[d] = lds64(s2 + (l0 + d) * C2 + 2 * p);
                    #pragma unroll
                    for (int k = 0; k < K3; k++) {
                        u64 w = lds64(sw3p + ((p * K3 + k) * C3 + co) * 2);
                        a0 = ffma2(w, sp[k], a0);
                        a1 = ffma2(w, sp[k + 1], a1);
                        a2 = ffma2(w, sp[k + 2], a2);
                        a3 = ffma2(w, sp[k + 3], a3);
                    }
                }
                u64 accs[4] = {a0, a1, a2, a3};
                unsigned bits = 0;
                #pragma unroll
                for (int q = 0; q < 4; q++) {
                    float lo, hi; unpack2(accs[q], lo, hi);
                    float h = __fadd_rn(lo, hi);
                    int lin = (l0 + q) * C3 + co;
                    float mn = lif_new_mem(m3[lin], h);
                    m3[lin] = mn;
                    if (mn > 1.0f) bits |= 1u << q;
                }
                if (bits) atomicOr(&mask3[co], bits << l0);
            }
        }
        __syncthreads();

        // ---------------- fc1 (1152->256) sparse gather, float2, 128 threads ----------------
        if (tid < 128) {
            int j2 = tid;  // outputs 2*j2, 2*j2+1
            u64 acc = *(const u64*)(fb1 + 2 * j2);
            #pragma unroll 4
            for (int r = 0; r < C3; r++) {
                unsigned m = mask3[r];   // uniform across threads
                const float* base = g_fw1T + r * (L3 * H1) + 2 * j2;
                while (m) {
                    int l = __ffs(m) - 1;
                    m &= m - 1;
                    acc = fadd2(acc, *(const u64*)(base + l * H1));
                }
            }
            float lo, hi; unpack2(acc, lo, hi);
            float mn0 = lif_new_mem(m4[2 * j2], lo);
            float mn1 = lif_new_mem(m4[2 * j2 + 1], hi);
            m4[2 * j2] = mn0;
            m4[2 * j2 + 1] = mn1;
            s4[2 * j2]     = (mn0 > 1.0f) ? 1.0f : 0.0f;
            s4[2 * j2 + 1] = (mn1 > 1.0f) ? 1.0f : 0.0f;
        }
        __syncthreads();

        // ---------------- fc2 (256->10) + LIF + output ----------------
        for (int j = warp; j < NC; j += 8) {
            float acc = 0.0f;
            #pragma unroll
            for (int q = 0; q < 8; q++) {
                int i = lane + 32 * q;
                acc = fmaf(fw2[j * H1 + i], s4[i], acc);
            }
            #pragma unroll
            for (int o = 16; o > 0; o >>= 1)
                acc += __shfl_down_sync(0xffffffff, acc, o);
            if (lane == 0) {
                acc += fb2[j];
                float mn = lif_new_mem(m5[j], acc);
                m5[j] = mn;
                out[(t * BATCH + b) * NC + j] = (mn > 1.0f) ? 1.0f : 0.0f;
            }
        }
        __syncthreads();
    }
}

extern "C" void kernel_launch(void* const* d_in, const int* in_sizes, int n_in,
                              void* d_out, int out_size) {
    const float* x   = (const float*)d_in[0];
    const float* w1  = (const float*)d_in[1];
    const float* b1  = (const float*)d_in[2];
    const float* w2  = (const float*)d_in[3];
    const float* b2  = (const float*)d_in[4];
    const float* w3  = (const float*)d_in[5];
    const float* b3  = (const float*)d_in[6];
    const float* fw1 = (const float*)d_in[7];
    const float* fb1 = (const float*)d_in[8];
    const float* fw2 = (const float*)d_in[9];
    const float* fb2 = (const float*)d_in[10];
    float* out = (float*)d_out;

    cudaFuncSetAttribute(snn_kernel, cudaFuncAttributeMaxDynamicSharedMemorySize, SMEM_BYTES);

    transpose_fw1_kernel<<<(H1 * F1 + 255) / 256, 256>>>(fw1);
    snn_kernel<<<BATCH, NTHREADS, SMEM_BYTES>>>(x, w1, b1, w2, b2, w3, b3,
                                                fb1, fw2, fb2, out);
}